// round 4
// baseline (speedup 1.0000x reference)
#include <cuda_runtime.h>
#include <cuda_fp16.h>
#include <cstdint>
#include <cstddef>

static constexpr int TOKENS = 8192;
static constexpr int INF    = 4096;
static constexpr int NF     = 4096;
static constexpr int RDIM   = 256;
static constexpr int KSEL   = 128;

__device__ __align__(16) uint16_t g_A[(size_t)TOKENS * INF];  // x fp16 [M][K]
__device__ __align__(16) uint16_t g_W[(size_t)NF * INF];      // W fp16 [N][K]

__device__ __forceinline__ uint32_t smem_u32(const void* p) {
    uint32_t a;
    asm("{ .reg .u64 t; cvta.to.shared.u64 t, %1; cvt.u32.u64 %0, t; }"
        : "=r"(a) : "l"(p));
    return a;
}

__device__ __forceinline__ void cp_async16(uint32_t dst, const void* src) {
    asm volatile("cp.async.cg.shared.global [%0], [%1], 16;"
                 :: "r"(dst), "l"(src) : "memory");
}

__device__ __forceinline__ uint32_t sw128(uint32_t off) {
    return off ^ ((off >> 3) & 0x70u);
}

#define LDMATRIX_X4(r0, r1, r2, r3, addr) \
    asm volatile("ldmatrix.sync.aligned.m8n8.x4.shared.b16 {%0,%1,%2,%3}, [%4];" \
                 : "=r"(r0), "=r"(r1), "=r"(r2), "=r"(r3) : "r"(addr))

#define MMA16816(c, a0, a1, a2, a3, b0, b1) \
    asm volatile("mma.sync.aligned.m16n8k16.row.col.f32.f16.f16.f32 " \
                 "{%0,%1,%2,%3}, {%4,%5,%6,%7}, {%8,%9}, {%0,%1,%2,%3};" \
                 : "+f"((c)[0]), "+f"((c)[1]), "+f"((c)[2]), "+f"((c)[3]) \
                 : "r"(a0), "r"(a1), "r"(a2), "r"(a3), "r"(b0), "r"(b1))

// --- Kernel 1: fp32 x -> fp16 g_A, 8 elems/thread ---
__global__ void convert_x_kernel(const float* __restrict__ x) {
    size_t t = (size_t)blockIdx.x * blockDim.x + threadIdx.x;
    const float4* in4 = reinterpret_cast<const float4*>(x);
    float4 a = in4[2 * t], b = in4[2 * t + 1];
    __half2 h0 = __floats2half2_rn(a.x, a.y), h1 = __floats2half2_rn(a.z, a.w);
    __half2 h2 = __floats2half2_rn(b.x, b.y), h3 = __floats2half2_rn(b.z, b.w);
    uint4 u;
    u.x = *reinterpret_cast<uint32_t*>(&h0);
    u.y = *reinterpret_cast<uint32_t*>(&h1);
    u.z = *reinterpret_cast<uint32_t*>(&h2);
    u.w = *reinterpret_cast<uint32_t*>(&h3);
    reinterpret_cast<uint4*>(g_A)[t] = u;
}

// --- Kernel 2: deterministic scatter into dense W (fp16, K-major) ---
// CTA per (r, o-half); thread owns a private smem column of 256 c-accums,
// duplicates in col_indices are summed sequentially in fp32 (deterministic).
__global__ void scatter_w_kernel(const float* __restrict__ values,
                                 const int* __restrict__ colidx) {
    extern __shared__ float acc[];  // [256 c][128 t]
    const int r = blockIdx.x >> 1, oh = blockIdx.x & 1, t = threadIdx.x;
    const int o = oh * 8 + (t >> 4), i = t & 15;
#pragma unroll 8
    for (int c = 0; c < 256; c++) acc[c * 128 + t] = 0.0f;
    const float* vbase = values + (size_t)r * (KSEL * 256) + o * 16 + i;
    const int* cb = colidx + r * KSEL;
    for (int k = 0; k < KSEL; k++) {
        int c = __ldg(cb + k);
        acc[c * 128 + t] += __ldg(vbase + (size_t)k * 256);
    }
    uint16_t* wrow = g_W + (size_t)(r * 16 + o) * INF + i;
#pragma unroll 4
    for (int c = 0; c < 256; c++)
        wrow[c * 16] = __half_as_ushort(__float2half_rn(acc[c * 128 + t]));
}

// --- Kernel 3: mma.sync fp16 GEMM, CTA 128x128, K-chunk 64, 4-stage pipe ---
static constexpr int STAGES      = 4;
static constexpr int STAGE_BYTES = 32768;  // A 128x64 f16 (16KB) + B 128x64 f16 (16KB)
static constexpr int GEMM_SMEM   = STAGES * STAGE_BYTES;  // 128 KB
static constexpr int NCHUNK      = INF / 64;              // 64

#define LOAD_STAGE(stage, chunk) do {                                   \
    uint32_t _ab = sb + (uint32_t)(stage) * STAGE_BYTES;                \
    uint32_t _bb = _ab + 16384;                                         \
    int _koff = (chunk) * 64;                                           \
    _Pragma("unroll")                                                   \
    for (int _j = 0; _j < 4; _j++) {                                    \
        cp_async16(_ab + swo[_j], a_src[_j] + _koff);                   \
        cp_async16(_bb + swo[_j], b_src[_j] + _koff);                   \
    }                                                                   \
    asm volatile("cp.async.commit_group;" ::: "memory");                \
} while (0)

__global__ void __launch_bounds__(256, 1)
gemm_f16_kernel(float* __restrict__ out) {
    extern __shared__ char smem[];
    const uint32_t sb = smem_u32(smem);
    const int tid = threadIdx.x, wid = tid >> 5, lid = tid & 31;
    const int wm = wid >> 2, wn = wid & 3;  // 2 x 4 warp grid

    const int m0 = blockIdx.y * 128, n0 = blockIdx.x * 128;

    // cp.async plan: 256 threads x 4 segs cover 128 rows x 8 x 16B per operand
    uint32_t swo[4];
    const uint16_t *a_src[4], *b_src[4];
#pragma unroll
    for (int j = 0; j < 4; j++) {
        int idx = tid + 256 * j, row = idx >> 3, seg = idx & 7;
        uint32_t off = (uint32_t)row * 128u + (uint32_t)seg * 16u;
        swo[j] = sw128(off);
        a_src[j] = g_A + (size_t)(m0 + row) * INF + seg * 8;
        b_src[j] = g_W + (size_t)(n0 + row) * INF + seg * 8;
    }

#pragma unroll
    for (int s = 0; s < 3; s++) LOAD_STAGE(s, s);

    float acc[4][4][4];
#pragma unroll
    for (int mt = 0; mt < 4; mt++)
#pragma unroll
        for (int nt = 0; nt < 4; nt++)
#pragma unroll
            for (int q = 0; q < 4; q++) acc[mt][nt][q] = 0.0f;

    // per-thread ldmatrix base rows (lane%16) and k-half (lane/16)*16B
    const uint32_t lrow = (uint32_t)(lid & 15);
    const uint32_t lkb  = (uint32_t)(lid >> 4) * 16u;

    for (int c = 0; c < NCHUNK; c++) {
        const uint32_t st = (uint32_t)(c & (STAGES - 1));
        asm volatile("cp.async.wait_group 2;" ::: "memory");
        __syncthreads();

        if (c + 3 < NCHUNK) {
            LOAD_STAGE((c + 3) & (STAGES - 1), c + 3);
        } else {
            asm volatile("cp.async.commit_group;" ::: "memory");
        }

        const uint32_t abase = sb + st * STAGE_BYTES;
        const uint32_t bbase = abase + 16384;

#pragma unroll
        for (int ks = 0; ks < 4; ks++) {
            const uint32_t kb = (uint32_t)ks * 32u + lkb;
            // B fragments: 2 x4 loads cover 4 n-tiles (n rows 0-31 of warp tile)
            uint32_t b0[4], b1[4];
            {
                uint32_t off = ((uint32_t)(wn * 32) + lrow) * 128u + kb;
                LDMATRIX_X4(b0[0], b0[1], b0[2], b0[3], bbase + sw128(off));
                off = ((uint32_t)(wn * 32 + 16) + lrow) * 128u + kb;
                LDMATRIX_X4(b1[0], b1[1], b1[2], b1[3], bbase + sw128(off));
            }
#pragma unroll
            for (int mt = 0; mt < 4; mt++) {
                uint32_t a0, a1, a2, a3;
                uint32_t off = ((uint32_t)(wm * 64 + mt * 16) + lrow) * 128u + kb;
                LDMATRIX_X4(a0, a1, a2, a3, abase + sw128(off));
                // ntile 0: (n0-7) b={r0,r2}; ntile 1: (n8-15) b={r1,r3}
                MMA16816(acc[mt][0], a0, a1, a2, a3, b0[0], b0[2]);
                MMA16816(acc[mt][1], a0, a1, a2, a3, b0[1], b0[3]);
                MMA16816(acc[mt][2], a0, a1, a2, a3, b1[0], b1[2]);
                MMA16816(acc[mt][3], a0, a1, a2, a3, b1[1], b1[3]);
            }
        }
    }

    // epilogue: direct register -> gmem
    const int tq = lid >> 2, tr = lid & 3;
#pragma unroll
    for (int mt = 0; mt < 4; mt++) {
#pragma unroll
        for (int h = 0; h < 2; h++) {
            int gm = m0 + wm * 64 + mt * 16 + h * 8 + tq;
            float* row = out + (size_t)gm * NF + n0 + wn * 32 + tr * 2;
#pragma unroll
            for (int nt = 0; nt < 4; nt++) {
                float2 v;
                v.x = acc[mt][nt][h * 2 + 0];
                v.y = acc[mt][nt][h * 2 + 1];
                *reinterpret_cast<float2*>(row + nt * 8) = v;
            }
        }
    }
}

extern "C" void kernel_launch(void* const* d_in, const int* in_sizes, int n_in,
                              void* d_out, int out_size) {
    const float* x      = (const float*)d_in[0];
    const float* values = (const float*)d_in[1];
    const int*   colidx = (const int*)d_in[2];
    float*       out    = (float*)d_out;

    cudaFuncSetAttribute(scatter_w_kernel,
                         cudaFuncAttributeMaxDynamicSharedMemorySize, 131072);
    cudaFuncSetAttribute(gemm_f16_kernel,
                         cudaFuncAttributeMaxDynamicSharedMemorySize, GEMM_SMEM);

    convert_x_kernel<<<16384, 256>>>(x);                   // 8192*4096 / (8*256)
    scatter_w_kernel<<<RDIM * 2, 128, 131072>>>(values, colidx);
    dim3 grid(NF / 128, TOKENS / 128);                     // (32, 64)
    gemm_f16_kernel<<<grid, 256, GEMM_SMEM>>>(out);
}

// round 5
// speedup vs baseline: 1.0920x; 1.0920x over previous
#include <cuda_runtime.h>
#include <cuda_fp16.h>
#include <cstdint>
#include <cstddef>

static constexpr int TOKENS = 8192;
static constexpr int INF    = 4096;
static constexpr int NF     = 4096;
static constexpr int RDIM   = 256;
static constexpr int KSEL   = 128;

__device__ __align__(16) uint16_t g_A[(size_t)TOKENS * INF];  // x fp16 [M][K]
__device__ __align__(16) uint16_t g_W[(size_t)NF * INF];      // W fp16 [N][K]

__device__ __forceinline__ uint32_t smem_u32(const void* p) {
    uint32_t a;
    asm("{ .reg .u64 t; cvta.to.shared.u64 t, %1; cvt.u32.u64 %0, t; }"
        : "=r"(a) : "l"(p));
    return a;
}

__device__ __forceinline__ void cp_async16(uint32_t dst, const void* src) {
    asm volatile("cp.async.cg.shared.global [%0], [%1], 16;"
                 :: "r"(dst), "l"(src) : "memory");
}

__device__ __forceinline__ uint32_t sw128(uint32_t off) {
    return off ^ ((off >> 3) & 0x70u);
}

#define LDMATRIX_X4(r0, r1, r2, r3, addr) \
    asm volatile("ldmatrix.sync.aligned.m8n8.x4.shared.b16 {%0,%1,%2,%3}, [%4];" \
                 : "=r"(r0), "=r"(r1), "=r"(r2), "=r"(r3) : "r"(addr))

#define MMA16816(c, a0, a1, a2, a3, b0, b1) \
    asm volatile("mma.sync.aligned.m16n8k16.row.col.f32.f16.f16.f32 " \
                 "{%0,%1,%2,%3}, {%4,%5,%6,%7}, {%8,%9}, {%0,%1,%2,%3};" \
                 : "+f"((c)[0]), "+f"((c)[1]), "+f"((c)[2]), "+f"((c)[3]) \
                 : "r"(a0), "r"(a1), "r"(a2), "r"(a3), "r"(b0), "r"(b1))

// --- Kernel 1: fp32 x -> fp16 g_A, 8 elems/thread ---
__global__ void convert_x_kernel(const float* __restrict__ x) {
    size_t t = (size_t)blockIdx.x * blockDim.x + threadIdx.x;
    const float4* in4 = reinterpret_cast<const float4*>(x);
    float4 a = in4[2 * t], b = in4[2 * t + 1];
    __half2 h0 = __floats2half2_rn(a.x, a.y), h1 = __floats2half2_rn(a.z, a.w);
    __half2 h2 = __floats2half2_rn(b.x, b.y), h3 = __floats2half2_rn(b.z, b.w);
    uint4 u;
    u.x = *reinterpret_cast<uint32_t*>(&h0);
    u.y = *reinterpret_cast<uint32_t*>(&h1);
    u.z = *reinterpret_cast<uint32_t*>(&h2);
    u.w = *reinterpret_cast<uint32_t*>(&h3);
    reinterpret_cast<uint4*>(g_A)[t] = u;
}

// --- Kernel 2: deterministic scatter into dense W (fp16, K-major) ---
__global__ void scatter_w_kernel(const float* __restrict__ values,
                                 const int* __restrict__ colidx) {
    extern __shared__ float acc[];  // [256 c][128 t]
    const int r = blockIdx.x >> 1, oh = blockIdx.x & 1, t = threadIdx.x;
    const int o = oh * 8 + (t >> 4), i = t & 15;
#pragma unroll 8
    for (int c = 0; c < 256; c++) acc[c * 128 + t] = 0.0f;
    const float* vbase = values + (size_t)r * (KSEL * 256) + o * 16 + i;
    const int* cb = colidx + r * KSEL;
    for (int k = 0; k < KSEL; k++) {
        int c = __ldg(cb + k);
        acc[c * 128 + t] += __ldg(vbase + (size_t)k * 256);
    }
    uint16_t* wrow = g_W + (size_t)(r * 16 + o) * INF + i;
#pragma unroll 4
    for (int c = 0; c < 256; c++)
        wrow[c * 16] = __half_as_ushort(__float2half_rn(acc[c * 128 + t]));
}

// --- Kernel 3: mma.sync fp16 GEMM ---
// CTA tile 128(M) x 256(N), warp tile 64x64 (2x4 warp grid), K-chunk 64,
// 4-stage cp.async pipeline (192 KB smem), fp32 accum.
static constexpr int STAGES      = 4;
static constexpr int A_BYTES     = 128 * 128;          // 128 rows x 64 f16
static constexpr int B_BYTES     = 256 * 128;          // 256 rows x 64 f16
static constexpr int STAGE_BYTES = A_BYTES + B_BYTES;  // 48 KB
static constexpr int GEMM_SMEM   = STAGES * STAGE_BYTES;  // 192 KB
static constexpr int NCHUNK      = INF / 64;           // 64

#define LOAD_STAGE(stage, chunk) do {                                    \
    uint32_t _ab = sb + (uint32_t)(stage) * STAGE_BYTES;                 \
    uint32_t _bb = _ab + A_BYTES;                                        \
    int _koff = (chunk) * 64;                                            \
    _Pragma("unroll")                                                    \
    for (int _j = 0; _j < 4; _j++)                                       \
        cp_async16(_ab + sw0 + _j * 4096u, asrc0 + (size_t)_j * 32 * INF + _koff); \
    _Pragma("unroll")                                                    \
    for (int _j = 0; _j < 8; _j++)                                       \
        cp_async16(_bb + sw0 + _j * 4096u, bsrc0 + (size_t)_j * 32 * INF + _koff); \
    asm volatile("cp.async.commit_group;" ::: "memory");                 \
} while (0)

__global__ void __launch_bounds__(256, 1)
gemm_f16_kernel(float* __restrict__ out) {
    extern __shared__ char smem[];
    const uint32_t sb = smem_u32(smem);
    const int tid = threadIdx.x, wid = tid >> 5, lid = tid & 31;
    const int wm = wid >> 2, wn = wid & 3;  // 2 x 4 warp grid

    const int m0 = blockIdx.y * 128, n0 = blockIdx.x * 256;

    // load plan: 256 threads cover 32 rows x 8 segs per step; row stride 32
    // keeps the SW128 offset linear (+32*128 per step, row&7 unchanged).
    const int row0 = tid >> 3, seg = tid & 7;
    const uint32_t sw0 = sw128((uint32_t)row0 * 128u + (uint32_t)seg * 16u);
    const uint16_t* asrc0 = g_A + (size_t)(m0 + row0) * INF + seg * 8;
    const uint16_t* bsrc0 = g_W + (size_t)(n0 + row0) * INF + seg * 8;

#pragma unroll
    for (int s = 0; s < 3; s++) LOAD_STAGE(s, s);

    float acc[4][8][4];
#pragma unroll
    for (int mt = 0; mt < 4; mt++)
#pragma unroll
        for (int nt = 0; nt < 8; nt++)
#pragma unroll
            for (int q = 0; q < 4; q++) acc[mt][nt][q] = 0.0f;

    const uint32_t lrow = (uint32_t)(lid & 15);
    const uint32_t lkb  = (uint32_t)(lid >> 4) * 16u;

    for (int c = 0; c < NCHUNK; c++) {
        const uint32_t st = (uint32_t)(c & (STAGES - 1));
        asm volatile("cp.async.wait_group 2;" ::: "memory");
        __syncthreads();

        if (c + 3 < NCHUNK) {
            LOAD_STAGE((c + 3) & (STAGES - 1), c + 3);
        } else {
            asm volatile("cp.async.commit_group;" ::: "memory");
        }

        const uint32_t abase = sb + st * STAGE_BYTES;
        const uint32_t bbase = abase + A_BYTES;

#pragma unroll
        for (int ks = 0; ks < 4; ks++) {
            const uint32_t kb = (uint32_t)ks * 32u + lkb;
            // B fragments: 4 x4-loads cover 8 n-tiles (64 n-rows of warp tile)
            uint32_t bf[4][4];
#pragma unroll
            for (int j = 0; j < 4; j++) {
                uint32_t off = ((uint32_t)(wn * 64 + j * 16) + lrow) * 128u + kb;
                LDMATRIX_X4(bf[j][0], bf[j][1], bf[j][2], bf[j][3],
                            bbase + sw128(off));
            }
#pragma unroll
            for (int mt = 0; mt < 4; mt++) {
                uint32_t a0, a1, a2, a3;
                uint32_t off = ((uint32_t)(wm * 64 + mt * 16) + lrow) * 128u + kb;
                LDMATRIX_X4(a0, a1, a2, a3, abase + sw128(off));
#pragma unroll
                for (int j = 0; j < 4; j++) {
                    MMA16816(acc[mt][2 * j + 0], a0, a1, a2, a3, bf[j][0], bf[j][2]);
                    MMA16816(acc[mt][2 * j + 1], a0, a1, a2, a3, bf[j][1], bf[j][3]);
                }
            }
        }
    }

    // epilogue: registers -> gmem (float2 stores)
    const int tq = lid >> 2, tr = lid & 3;
#pragma unroll
    for (int mt = 0; mt < 4; mt++) {
#pragma unroll
        for (int h = 0; h < 2; h++) {
            int gm = m0 + wm * 64 + mt * 16 + h * 8 + tq;
            float* row = out + (size_t)gm * NF + n0 + wn * 64 + tr * 2;
#pragma unroll
            for (int nt = 0; nt < 8; nt++) {
                float2 v;
                v.x = acc[mt][nt][h * 2 + 0];
                v.y = acc[mt][nt][h * 2 + 1];
                *reinterpret_cast<float2*>(row + nt * 8) = v;
            }
        }
    }
}

extern "C" void kernel_launch(void* const* d_in, const int* in_sizes, int n_in,
                              void* d_out, int out_size) {
    const float* x      = (const float*)d_in[0];
    const float* values = (const float*)d_in[1];
    const int*   colidx = (const int*)d_in[2];
    float*       out    = (float*)d_out;

    cudaFuncSetAttribute(scatter_w_kernel,
                         cudaFuncAttributeMaxDynamicSharedMemorySize, 131072);
    cudaFuncSetAttribute(gemm_f16_kernel,
                         cudaFuncAttributeMaxDynamicSharedMemorySize, GEMM_SMEM);

    convert_x_kernel<<<16384, 256>>>(x);
    scatter_w_kernel<<<RDIM * 2, 128, 131072>>>(values, colidx);
    dim3 grid(NF / 256, TOKENS / 128);  // (16, 64)
    gemm_f16_kernel<<<grid, 256, GEMM_SMEM>>>(out);
}